// round 9
// baseline (speedup 1.0000x reference)
#include <cuda_runtime.h>
#include <cstdint>

#define TABLE_SIZE 524288u          // 2^19 -> modulo is a mask
#define NUM_LEVELS 16
#define N_POINTS (1u << 20)
#define HASH_PRIME 2654435761u

#define BINS_PER_AXIS 256u
#define NBINS (BINS_PER_AXIS * BINS_PER_AXIS)   // 65536 spatial bins

// -------- allocation-free scratch (device globals) --------
__device__ uint32_t g_hist[NBINS];
__device__ uint32_t g_cursor[NBINS];     // local-exclusive within row after scanA
__device__ uint32_t g_rowsum[BINS_PER_AXIS];
__device__ float4   g_spts[N_POINTS];    // sorted {x, y, idx_bits, unused}

// scalings: floor(16 * (2^0.4)^l) in fp32, matching the reference exactly.
__constant__ float kScale[NUM_LEVELS] = {
    16.0f, 21.0f, 27.0f, 36.0f, 48.0f, 64.0f, 84.0f, 111.0f,
    147.0f, 194.0f, 256.0f, 337.0f, 445.0f, 588.0f, 776.0f, 1024.0f
};

__device__ __forceinline__ uint32_t bin_key(float xv, float yv)
{
    uint32_t kx = (uint32_t)(xv * 256.0f);
    uint32_t ky = (uint32_t)(yv * 256.0f);
    kx = kx > 255u ? 255u : kx;
    ky = ky > 255u ? 255u : ky;
    return (ky << 8) | kx;               // row-major; bin>>8 = ky
}

// ---------------- sort pipeline ----------------
__global__ void zero_hist_kernel()
{
    g_hist[blockIdx.x * 256u + threadIdx.x] = 0u;
}

// 4 points per thread (two float4 loads)
__global__ void hist_kernel(const float4* __restrict__ x4)
{
    const uint32_t i = (blockIdx.x * 256u + threadIdx.x) * 2u;
    const float4 a = __ldg(&x4[i]);
    const float4 b = __ldg(&x4[i + 1u]);
    atomicAdd(&g_hist[bin_key(a.x, a.y)], 1u);
    atomicAdd(&g_hist[bin_key(a.z, a.w)], 1u);
    atomicAdd(&g_hist[bin_key(b.x, b.y)], 1u);
    atomicAdd(&g_hist[bin_key(b.z, b.w)], 1u);
}

// scanA: 256 blocks; block b scans bins [b*256, b*256+256) -> local exclusive
__global__ void scanA_kernel()
{
    __shared__ uint32_t s[256];
    const uint32_t t = threadIdx.x;
    const uint32_t i = blockIdx.x * 256u + t;
    const uint32_t v = g_hist[i];
    s[t] = v;
    __syncthreads();
    #pragma unroll
    for (uint32_t off = 1u; off < 256u; off <<= 1) {
        uint32_t u = (t >= off) ? s[t - off] : 0u;
        __syncthreads();
        s[t] += u;
        __syncthreads();
    }
    g_cursor[i] = s[t] - v;                     // exclusive within row
    if (t == 255u) g_rowsum[blockIdx.x] = s[t]; // row total
}

// scatter: block redundantly scans the 256 row sums once (amortized over
// 1024 points), then scatters 4 points per thread (MLP=4 atomic chains).
__global__ void scatter_kernel(const float2* __restrict__ x)
{
    __shared__ uint32_t sro[256];
    const uint32_t t = threadIdx.x;

    const uint32_t rv = g_rowsum[t];
    sro[t] = rv;
    __syncthreads();
    #pragma unroll
    for (uint32_t off = 1u; off < 256u; off <<= 1) {
        uint32_t u = (t >= off) ? sro[t - off] : 0u;
        __syncthreads();
        sro[t] += u;
        __syncthreads();
    }
    const uint32_t excl = sro[t] - rv;
    __syncthreads();
    sro[t] = excl;                               // row-offset table
    __syncthreads();

    const uint32_t base = blockIdx.x * 1024u + t;

    float2 xp[4];
    uint32_t bin[4], pos[4];
    #pragma unroll
    for (uint32_t k = 0; k < 4u; ++k)
        xp[k] = __ldg(&x[base + k * 256u]);
    #pragma unroll
    for (uint32_t k = 0; k < 4u; ++k)
        bin[k] = bin_key(xp[k].x, xp[k].y);
    #pragma unroll
    for (uint32_t k = 0; k < 4u; ++k)
        pos[k] = atomicAdd(&g_cursor[bin[k]], 1u);
    #pragma unroll
    for (uint32_t k = 0; k < 4u; ++k)
        g_spts[pos[k] + sro[bin[k] >> 8]] =
            make_float4(xp[k].x, xp[k].y,
                        __uint_as_float(base + k * 256u), 0.0f);
}

// ---------------- main encode kernel ----------------
// lane = sorted point; warp = 32 spatially-adjacent points; loop over levels.
// Transpose through smem with 9-float2 stride: bank-pair = (9q+p) mod 16 ->
// exactly 2-way (the 2-phase floor) on both STS.64 and LDS.64.
#define M_BLOCK 256
#define ROW_F2 9                     // float2 stride per point per half

__global__ __launch_bounds__(M_BLOCK)
void hash_encode_kernel(const float4* __restrict__ spts,
                        const float2* __restrict__ table,
                        float2* __restrict__ out)
{
    __shared__ float2 s_buf[M_BLOCK / 32][32 * ROW_F2];

    const uint32_t tid  = threadIdx.x;
    const uint32_t lane = tid & 31u;
    float2* const srow  = s_buf[tid >> 5];

    const uint32_t p  = blockIdx.x * M_BLOCK + tid;   // sorted position
    const float4 pt   = __ldg(&spts[p]);              // coalesced LDG.128.NC
    const uint32_t og = __float_as_uint(pt.z);        // original index

    const uint32_t pc = lane >> 3;       // 0..3 point-group for store passes
    const uint32_t pp = lane & 7u;       // piece 0..7

    #pragma unroll
    for (uint32_t half = 0; half < 2u; ++half) {
        #pragma unroll
        for (uint32_t h = 0; h < 8u; ++h) {
            const uint32_t l = half * 8u + h;
            const float s  = kScale[l];
            const float sx = pt.x * s;
            const float sy = pt.y * s;

            const float fxf = floorf(sx);
            const float fyf = floorf(sy);
            const uint32_t fx = (uint32_t)(int32_t)fxf;
            const uint32_t fy = (uint32_t)(int32_t)fyf;
            const uint32_t cx = (uint32_t)(int32_t)ceilf(sx);
            const uint32_t cy = (uint32_t)(int32_t)ceilf(sy);
            const float ox = sx - fxf;
            const float oy = sy - fyf;

            const uint32_t base = l * TABLE_SIZE;
            const uint32_t hyc  = cy * HASH_PRIME;
            const uint32_t hyf  = fy * HASH_PRIME;
            // v0=(cx,cy) v1=(cx,fy) v2=(fx,cy) v3=(fx,fy)
            const uint32_t h0 = ((cx ^ hyc) & (TABLE_SIZE - 1u)) + base;
            const uint32_t h1 = ((cx ^ hyf) & (TABLE_SIZE - 1u)) + base;
            const uint32_t h2 = ((fx ^ hyc) & (TABLE_SIZE - 1u)) + base;
            const uint32_t h3 = ((fx ^ hyf) & (TABLE_SIZE - 1u)) + base;

            const float2 f0 = __ldg(&table[h0]);
            const float2 f1 = __ldg(&table[h1]);
            const float2 f2 = __ldg(&table[h2]);
            const float2 f3 = __ldg(&table[h3]);

            const float omx = 1.0f - ox;
            const float omy = 1.0f - oy;
            float2 e;
            e.x = (f0.x * ox + f3.x * omx) * oy + (f1.x * ox + f2.x * omx) * omy;
            e.y = (f0.y * ox + f3.y * omx) * oy + (f1.y * ox + f2.y * omx) * omy;

            srow[lane * ROW_F2 + h] = e;      // STS.64, 2-way max
        }
        __syncwarp();

        // transpose out: pass covers points {pc*8, .., pc*8+7}
        #pragma unroll
        for (uint32_t pass = 0; pass < 8u; ++pass) {
            const uint32_t q = pc * 8u + pass;               // warp point
            const float2 v = srow[q * ROW_F2 + pp];          // LDS.64, 2-way max
            const uint32_t oq = __shfl_sync(0xffffffffu, og, (int)q);
            out[(size_t)oq * 16u + half * 8u + pp] = v;      // STG.64, 4 rows/instr
        }
        __syncwarp();
    }
}

extern "C" void kernel_launch(void* const* d_in, const int* in_sizes, int n_in,
                              void* d_out, int out_size)
{
    const float2* x     = (const float2*)d_in[0];   // (N_POINTS, 2) float32
    const float2* table = (const float2*)d_in[1];   // (TABLE_SIZE*16, 2) float32
    float2* out = (float2*)d_out;                   // (N_POINTS, 32) float32

    float4* spts;
    cudaGetSymbolAddress((void**)&spts, g_spts);

    zero_hist_kernel<<<NBINS / 256, 256>>>();
    hist_kernel     <<<N_POINTS / 1024, 256>>>((const float4*)x);
    scanA_kernel    <<<256, 256>>>();
    scatter_kernel  <<<N_POINTS / 1024, 256>>>(x);
    hash_encode_kernel<<<N_POINTS / M_BLOCK, M_BLOCK>>>(spts, table, out);
}

// round 10
// speedup vs baseline: 1.0245x; 1.0245x over previous
#include <cuda_runtime.h>
#include <cstdint>

#define TABLE_SIZE 524288u          // 2^19 -> modulo is a mask
#define NUM_LEVELS 16
#define N_POINTS (1u << 20)
#define HASH_PRIME 2654435761u

#define BINS_PER_AXIS 256u
#define NBINS (BINS_PER_AXIS * BINS_PER_AXIS)   // 65536 spatial bins

// -------- allocation-free scratch (device globals) --------
__device__ uint32_t g_hist[NBINS];
__device__ uint32_t g_cursor[NBINS];     // exclusive within row after scanA
__device__ uint32_t g_rowsum[BINS_PER_AXIS];
__device__ uint32_t g_rank[N_POINTS];    // within-bin rank from hist pass
__device__ float4   g_spts[N_POINTS];    // sorted {x, y, idx_bits, unused}

// scalings: floor(16 * (2^0.4)^l) in fp32, matching the reference exactly.
__constant__ float kScale[NUM_LEVELS] = {
    16.0f, 21.0f, 27.0f, 36.0f, 48.0f, 64.0f, 84.0f, 111.0f,
    147.0f, 194.0f, 256.0f, 337.0f, 445.0f, 588.0f, 776.0f, 1024.0f
};

__device__ __forceinline__ uint32_t bin_key(float xv, float yv)
{
    uint32_t kx = (uint32_t)(xv * 256.0f);
    uint32_t ky = (uint32_t)(yv * 256.0f);
    kx = kx > 255u ? 255u : kx;
    ky = ky > 255u ? 255u : ky;
    return (ky << 8) | kx;               // row-major; bin>>8 = ky
}

// ---------------- sort pipeline ----------------
__global__ void zero_hist_kernel()
{
    g_hist[blockIdx.x * 256u + threadIdx.x] = 0u;
}

// histogram + per-point within-bin rank (the atomic's return value)
__global__ void hist_kernel(const float2* __restrict__ x)
{
    const uint32_t p = blockIdx.x * 256u + threadIdx.x;
    const float2 xp = __ldg(&x[p]);
    g_rank[p] = atomicAdd(&g_hist[bin_key(xp.x, xp.y)], 1u);
}

// scanA: 256 blocks; block b scans bins [b*256, b*256+256) -> local exclusive
__global__ void scanA_kernel()
{
    __shared__ uint32_t s[256];
    const uint32_t t = threadIdx.x;
    const uint32_t i = blockIdx.x * 256u + t;
    const uint32_t v = g_hist[i];
    s[t] = v;
    __syncthreads();
    #pragma unroll
    for (uint32_t off = 1u; off < 256u; off <<= 1) {
        uint32_t u = (t >= off) ? s[t - off] : 0u;
        __syncthreads();
        s[t] += u;
        __syncthreads();
    }
    g_cursor[i] = s[t] - v;                     // exclusive within row
    if (t == 255u) g_rowsum[blockIdx.x] = s[t]; // row total
}

// scatter: ATOMIC-FREE. pos = cursor[bin] + rowoff[ky] + rank[p].
// Block redundantly scans the 256 row sums in smem (cheap, parallel).
__global__ void scatter_kernel(const float2* __restrict__ x)
{
    __shared__ uint32_t sro[256];
    const uint32_t t = threadIdx.x;

    const uint32_t rv = g_rowsum[t];
    sro[t] = rv;
    __syncthreads();
    #pragma unroll
    for (uint32_t off = 1u; off < 256u; off <<= 1) {
        uint32_t u = (t >= off) ? sro[t - off] : 0u;
        __syncthreads();
        sro[t] += u;
        __syncthreads();
    }
    const uint32_t excl = sro[t] - rv;
    __syncthreads();
    sro[t] = excl;                               // row-offset table
    __syncthreads();

    const uint32_t p = blockIdx.x * 256u + t;
    const float2 xp = __ldg(&x[p]);              // coalesced
    const uint32_t rk = g_rank[p];               // coalesced
    const uint32_t bin = bin_key(xp.x, xp.y);
    const uint32_t pos = __ldg(&g_cursor[bin]) + sro[bin >> 8] + rk;
    g_spts[pos] = make_float4(xp.x, xp.y, __uint_as_float(p), 0.0f);
}

// ---------------- main encode kernel ----------------
// lane = sorted point; warp = 32 spatially-adjacent points; loop over levels.
// Transpose through smem with 9-float2 stride: bank-pair = (9q+p) mod 16 ->
// exactly 2-way (the 2-phase floor) on both STS.64 and LDS.64.
#define M_BLOCK 256
#define ROW_F2 9                     // float2 stride per point per half

__global__ __launch_bounds__(M_BLOCK)
void hash_encode_kernel(const float4* __restrict__ spts,
                        const float2* __restrict__ table,
                        float2* __restrict__ out)
{
    __shared__ float2 s_buf[M_BLOCK / 32][32 * ROW_F2];

    const uint32_t tid  = threadIdx.x;
    const uint32_t lane = tid & 31u;
    float2* const srow  = s_buf[tid >> 5];

    const uint32_t p  = blockIdx.x * M_BLOCK + tid;   // sorted position
    const float4 pt   = __ldg(&spts[p]);              // coalesced LDG.128.NC
    const uint32_t og = __float_as_uint(pt.z);        // original index

    const uint32_t pc = lane >> 3;       // 0..3 point-group for store passes
    const uint32_t pp = lane & 7u;       // piece 0..7

    #pragma unroll
    for (uint32_t half = 0; half < 2u; ++half) {
        #pragma unroll
        for (uint32_t h = 0; h < 8u; ++h) {
            const uint32_t l = half * 8u + h;
            const float s  = kScale[l];
            const float sx = pt.x * s;
            const float sy = pt.y * s;

            const float fxf = floorf(sx);
            const float fyf = floorf(sy);
            const uint32_t fx = (uint32_t)(int32_t)fxf;
            const uint32_t fy = (uint32_t)(int32_t)fyf;
            const uint32_t cx = (uint32_t)(int32_t)ceilf(sx);
            const uint32_t cy = (uint32_t)(int32_t)ceilf(sy);
            const float ox = sx - fxf;
            const float oy = sy - fyf;

            const uint32_t base = l * TABLE_SIZE;
            const uint32_t hyc  = cy * HASH_PRIME;
            const uint32_t hyf  = fy * HASH_PRIME;
            // v0=(cx,cy) v1=(cx,fy) v2=(fx,cy) v3=(fx,fy)
            const uint32_t h0 = ((cx ^ hyc) & (TABLE_SIZE - 1u)) + base;
            const uint32_t h1 = ((cx ^ hyf) & (TABLE_SIZE - 1u)) + base;
            const uint32_t h2 = ((fx ^ hyc) & (TABLE_SIZE - 1u)) + base;
            const uint32_t h3 = ((fx ^ hyf) & (TABLE_SIZE - 1u)) + base;

            const float2 f0 = __ldg(&table[h0]);
            const float2 f1 = __ldg(&table[h1]);
            const float2 f2 = __ldg(&table[h2]);
            const float2 f3 = __ldg(&table[h3]);

            const float omx = 1.0f - ox;
            const float omy = 1.0f - oy;
            float2 e;
            e.x = (f0.x * ox + f3.x * omx) * oy + (f1.x * ox + f2.x * omx) * omy;
            e.y = (f0.y * ox + f3.y * omx) * oy + (f1.y * ox + f2.y * omx) * omy;

            srow[lane * ROW_F2 + h] = e;      // STS.64, 2-way max
        }
        __syncwarp();

        // transpose out: pass covers points {pc*8, .., pc*8+7}
        #pragma unroll
        for (uint32_t pass = 0; pass < 8u; ++pass) {
            const uint32_t q = pc * 8u + pass;               // warp point
            const float2 v = srow[q * ROW_F2 + pp];          // LDS.64, 2-way max
            const uint32_t oq = __shfl_sync(0xffffffffu, og, (int)q);
            out[(size_t)oq * 16u + half * 8u + pp] = v;      // STG.64, 4 rows/instr
        }
        __syncwarp();
    }
}

extern "C" void kernel_launch(void* const* d_in, const int* in_sizes, int n_in,
                              void* d_out, int out_size)
{
    const float2* x     = (const float2*)d_in[0];   // (N_POINTS, 2) float32
    const float2* table = (const float2*)d_in[1];   // (TABLE_SIZE*16, 2) float32
    float2* out = (float2*)d_out;                   // (N_POINTS, 32) float32

    float4* spts;
    cudaGetSymbolAddress((void**)&spts, g_spts);

    zero_hist_kernel<<<NBINS / 256, 256>>>();
    hist_kernel     <<<N_POINTS / 256, 256>>>(x);
    scanA_kernel    <<<256, 256>>>();
    scatter_kernel  <<<N_POINTS / 256, 256>>>(x);
    hash_encode_kernel<<<N_POINTS / M_BLOCK, M_BLOCK>>>(spts, table, out);
}